// round 11
// baseline (speedup 1.0000x reference)
#include <cuda_runtime.h>
#include <cuda_bf16.h>
#include <cstdint>

#define BB 16
#define DD 64
#define NN 256
#define RR 32
#define HDIM 128
#define STEPS 5
#define BDN (BB*DD*NN)

// bf16 smem pitches (elements); byte pitch/16 odd -> conflict-free ldmatrix
#define XN_P 72    // x [n][d]          144 B
#define MT_P 72    // M^T [d2][d1]      144 B
#define W1C_P 72   // W1 chunk [hl][d]  144 B (32 rows)
#define W2C_P 40   // W2 chunk [d][hl]   80 B (64 rows)

// byte offsets into dynamic smem (16B aligned)
#define OFF_XN   0        // 256*144 = 36864
#define OFF_M    36864    // Phase A: M 64*144 = 9216   (union)
#define OFF_W1C  36864    // Phase C: W1 chunk 32*144 = 4608
#define OFF_W2C  41472    // Phase C: W2 chunk 64*80  = 5120
#define OFF_E    46592
#define OFF_F    47616
#define OFF_U    48640
#define OFF_V    48896
#define OFF_PL   49152
#define OFF_HI   49408
#define OFF_GT   49920
#define SMEM_BYTES 50048

// 1/sqrt(128) * log2(e): softmax done in exp2 domain
#define SCL2 0.1275187959554910f

// ---------------- device globals -------------------------------------------
__device__ float g_x[2][BDN];          // state, layout [b][n][d], fp32
__device__ float g_M[RR*DD*DD];
__device__ float g_u[RR*DD];
__device__ float g_v[RR*DD];
__device__ float g_c[RR];
__device__ float g_t[(size_t)RR*BDN];  // per-rule deltas [r][b][n][d]

// ---------------- helpers ---------------------------------------------------
__device__ __forceinline__ void ldsm4(uint32_t* r, uint32_t sa) {
    asm volatile("ldmatrix.sync.aligned.m8n8.x4.shared.b16 {%0,%1,%2,%3}, [%4];"
        : "=r"(r[0]), "=r"(r[1]), "=r"(r[2]), "=r"(r[3]) : "r"(sa));
}
__device__ __forceinline__ void ldsm4t(uint32_t* r, uint32_t sa) {
    asm volatile("ldmatrix.sync.aligned.m8n8.x4.trans.shared.b16 {%0,%1,%2,%3}, [%4];"
        : "=r"(r[0]), "=r"(r[1]), "=r"(r[2]), "=r"(r[3]) : "r"(sa));
}
__device__ __forceinline__ void mma16(float* c, const uint32_t* a,
                                      uint32_t b0, uint32_t b1) {
    asm volatile("mma.sync.aligned.m16n8k16.row.col.f32.bf16.bf16.f32 "
        "{%0,%1,%2,%3}, {%4,%5,%6,%7}, {%8,%9}, {%0,%1,%2,%3};"
        : "+f"(c[0]), "+f"(c[1]), "+f"(c[2]), "+f"(c[3])
        : "r"(a[0]), "r"(a[1]), "r"(a[2]), "r"(a[3]), "r"(b0), "r"(b1));
}
__device__ __forceinline__ uint32_t pbf2(float lo, float hi) {
    __nv_bfloat162 h = __floats2bfloat162_rn(lo, hi);
    return *reinterpret_cast<uint32_t*>(&h);
}
__device__ __forceinline__ float ex2(float x) {
    float y; asm("ex2.approx.f32 %0, %1;" : "=f"(y) : "f"(x)); return y;
}

// ---------------- init: symbols [b][d][n] -> g_x[0] as [b][n][d] -------------
__global__ void k_init(const float* __restrict__ sym) {
    int i = blockIdx.x * 256 + threadIdx.x;
    int b = i >> 14, rem = i & 16383, n = rem >> 6, d = rem & 63;
    g_x[0][i] = sym[b*16384 + d*256 + n];
}

// ---------------- precompute M = Wq Wk^T ------------------------------------
__global__ void k_precM(const float* __restrict__ Wq, const float* __restrict__ Wk) {
    int i = blockIdx.x * 256 + threadIdx.x;
    int d2 = i & 63, d1 = (i >> 6) & 63, r = i >> 12;
    const float* a = Wq + (r*DD + d1) * HDIM;
    const float* bkk = Wk + (r*DD + d2) * HDIM;
    float s = 0.f;
#pragma unroll 8
    for (int h = 0; h < HDIM; h++) s = fmaf(a[h], bkk[h], s);
    g_M[i] = s;
}

__global__ void k_precUVC(const float* __restrict__ Wq, const float* __restrict__ bq,
                          const float* __restrict__ Wk, const float* __restrict__ bk) {
    int r = blockIdx.x, d = threadIdx.x;
    float su = 0.f, sv = 0.f;
    const float* wqr = Wq + (r*DD + d) * HDIM;
    const float* wkr = Wk + (r*DD + d) * HDIM;
    const float* bqr = bq + r * HDIM;
    const float* bkr = bk + r * HDIM;
#pragma unroll 8
    for (int h = 0; h < HDIM; h++) {
        su = fmaf(wqr[h], bkr[h], su);
        sv = fmaf(bqr[h], wkr[h], sv);
    }
    g_u[r*DD + d] = su;
    g_v[r*DD + d] = sv;
    if (d == 0) {
        float sc = 0.f;
        for (int h = 0; h < HDIM; h++) sc = fmaf(bqr[h], bkr[h], sc);
        g_c[r] = sc;
    }
}

// ---------------- fused rule kernel: 4 CTAs per (b,r), 64 rows each ----------
__global__ void __launch_bounds__(128, 4)
k_rule(int cur,
       const float* __restrict__ W1g, const float* __restrict__ b1g,
       const float* __restrict__ W2g, const float* __restrict__ b2g,
       const float* __restrict__ Wg1, const float* __restrict__ bg1,
       const float* __restrict__ Wg2, const float* __restrict__ bg2) {
    extern __shared__ char smb[];
    const uint32_t sbu = (uint32_t)__cvta_generic_to_shared(smb);
    __nv_bfloat16* xNb = (__nv_bfloat16*)(smb + OFF_XN);
    float* eS    = (float*)(smb + OFF_E);    // (e + c) * SCL2 per token
    float* fS    = (float*)(smb + OFF_F);    // f * SCL2 per key
    float* uS    = (float*)(smb + OFF_U);
    float* vS    = (float*)(smb + OFF_V);
    float* poolS = (float*)(smb + OFF_PL);
    float* hidS  = (float*)(smb + OFF_HI);
    float* gateS = (float*)(smb + OFF_GT);

    const int t = threadIdx.x;
    const int lane = t & 31, w = t >> 5;        // 4 warps
    const int g = lane >> 2, t4 = lane & 3;
    const int idx = blockIdx.x >> 2, rq = blockIdx.x & 3;
    const int r = idx & (RR - 1), b = idx >> 5;
    const int row0 = rq * 64 + w * 16;          // this warp's 16 query rows

    // ldmatrix lane offsets
    const int aRow = lane & 15;                            // A x4
    const int aKof = (lane >> 4) << 3;
    const int bRow = (lane & 7) + ((lane >> 4) << 3);      // B x4 (normal)
    const int bKof = ((lane >> 3) & 1) << 3;
    const int tR   = (lane & 7) + (((lane >> 3) & 1) << 3); // B x4 (trans)
    const int tC   = ((lane >> 4) & 1) << 3;

    const float* xg = g_x[cur] + (size_t)b * NN * DD;

    // ---- prologue: stage x (256 tokens), M^T, u, v -------------------------
    for (int j = t; j < NN*DD/2; j += 128) {
        int n = j >> 5, d2 = (j & 31) * 2;
        *(uint32_t*)(smb + OFF_XN + (n*XN_P + d2)*2) = pbf2(xg[n*DD + d2], xg[n*DD + d2 + 1]);
    }
    for (int i = t; i < DD*DD; i += 128) {
        int d1 = i >> 6, d2 = i & 63;
        ((__nv_bfloat16*)(smb + OFF_M))[d2*MT_P + d1] = __float2bfloat16_rn(g_M[r*DD*DD + i]);
    }
    if (t < DD) { uS[t] = g_u[r*DD + t]; vS[t] = g_v[r*DD + t]; }
    __syncthreads();

    // ---- e/f for all 256 tokens (2 per thread) -----------------------------
    for (int tok = t; tok < NN; tok += 128) {
        float ea = 0.f, fa = 0.f;
#pragma unroll 8
        for (int d = 0; d < DD; d++) {
            float xv = __bfloat162float(xNb[tok*XN_P + d]);
            ea = fmaf(xv, uS[d], ea);
            fa = fmaf(xv, vS[d], fa);
        }
        eS[tok] = (ea + g_c[r]) * SCL2;
        fS[tok] = fa * SCL2;
    }
    __syncthreads();
    // ---- pooled mean: 2 threads per channel --------------------------------
    {
        int d = t >> 1, hf = t & 1;
        float s = 0.f;
#pragma unroll 8
        for (int n = hf*128; n < hf*128 + 128; n++) s += __bfloat162float(xNb[n*XN_P + d]);
        s += __shfl_xor_sync(~0u, s, 1);
        if (hf == 0) poolS[d] = s * (1.f/NN);
    }
    __syncthreads();
    {   // gate hidden: one h per thread (128 threads)
        float acc = bg1[t];
#pragma unroll 8
        for (int d = 0; d < DD; d++) acc = fmaf(poolS[d], __ldg(&Wg1[d*HDIM + t]), acc);
        hidS[t] = fmaxf(acc, 0.f);
    }
    __syncthreads();
    if (t < RR) {
        float lg = bg2[t];
#pragma unroll 8
        for (int j = 0; j < HDIM; j++) lg = fmaf(hidS[j], __ldg(&Wg2[j*RR + t]), lg);
        float m = lg;
#pragma unroll
        for (int o = 16; o > 0; o >>= 1) m = fmaxf(m, __shfl_xor_sync(~0u, m, o));
        float e = __expf(lg - m), ss = e;
#pragma unroll
        for (int o = 16; o > 0; o >>= 1) ss += __shfl_xor_sync(~0u, ss, o);
        gateS[t] = e / ss;
    }
    __syncthreads();

    // ---- Phase A: sx = X @ M -> registers, repack to A frags ----------------
    uint32_t asx[4][4];
    {
        uint32_t ax[4][4];
#pragma unroll
        for (int k0 = 0; k0 < 4; k0++)
            ldsm4(ax[k0], sbu + OFF_XN + ((row0 + aRow)*XN_P + k0*16 + aKof)*2);
        float SA[8][4];
#pragma unroll
        for (int nt = 0; nt < 8; nt++)
#pragma unroll
            for (int i = 0; i < 4; i++) SA[nt][i] = 0.f;
        uint32_t mb_[2][4][4];
#pragma unroll
        for (int p = 0; p < 4; p++)
            ldsm4(mb_[0][p], sbu + OFF_M + ((p*16 + bRow)*MT_P + bKof)*2);
#pragma unroll
        for (int k0 = 0; k0 < 4; k0++) {
            if (k0 < 3)
#pragma unroll
                for (int p = 0; p < 4; p++)
                    ldsm4(mb_[(k0+1)&1][p],
                          sbu + OFF_M + ((p*16 + bRow)*MT_P + (k0+1)*16 + bKof)*2);
#pragma unroll
            for (int p = 0; p < 4; p++) {
                mma16(SA[2*p],   ax[k0], mb_[k0&1][p][0], mb_[k0&1][p][1]);
                mma16(SA[2*p+1], ax[k0], mb_[k0&1][p][2], mb_[k0&1][p][3]);
            }
        }
#pragma unroll
        for (int j = 0; j < 4; j++) {
            asx[j][0] = pbf2(SA[2*j][0],   SA[2*j][1]);
            asx[j][1] = pbf2(SA[2*j][2],   SA[2*j][3]);
            asx[j][2] = pbf2(SA[2*j+1][0], SA[2*j+1][1]);
            asx[j][3] = pbf2(SA[2*j+1][2], SA[2*j+1][3]);
        }
    }

    // ---- Phase B: attention, 32-wide key blocks, pipelined ------------------
    float CA[8][4];
    float Lr[2] = {0.f, 0.f};
#pragma unroll
    for (int nt = 0; nt < 8; nt++)
#pragma unroll
        for (int i = 0; i < 4; i++) CA[nt][i] = 0.f;
    {
#pragma unroll 1
        for (int j = 0; j < 8; j++) {
            const int mb = j * 32;
            float SB[4][4];
#pragma unroll
            for (int nt = 0; nt < 4; nt++)
#pragma unroll
                for (int i = 0; i < 4; i++) SB[nt][i] = 0.f;
            // S = sx @ X^T (32 key cols), double-buffered B loads
            {
                uint32_t bb[2][2][4];
#pragma unroll
                for (int p = 0; p < 2; p++)
                    ldsm4(bb[0][p], sbu + OFF_XN + ((mb + p*16 + bRow)*XN_P + bKof)*2);
#pragma unroll
                for (int k0 = 0; k0 < 4; k0++) {
                    if (k0 < 3)
#pragma unroll
                        for (int p = 0; p < 2; p++)
                            ldsm4(bb[(k0+1)&1][p],
                                  sbu + OFF_XN + ((mb + p*16 + bRow)*XN_P + (k0+1)*16 + bKof)*2);
#pragma unroll
                    for (int p = 0; p < 2; p++) {
                        mma16(SB[2*p],   asx[k0], bb[k0&1][p][0], bb[k0&1][p][1]);
                        mma16(SB[2*p+1], asx[k0], bb[k0&1][p][2], bb[k0&1][p][3]);
                    }
                }
            }
            // p = exp2(S*SCL2 + e' + f');  Lr += p
#pragma unroll
            for (int hb = 0; hb < 2; hb++) {
                const float er = eS[row0 + hb*8 + g];
#pragma unroll
                for (int nt = 0; nt < 4; nt++)
#pragma unroll
                    for (int i2 = 0; i2 < 2; i2++) {
                        float ef = er + fS[mb + nt*8 + 2*t4 + i2];
                        float p = ex2(fmaf(SB[nt][hb*2 + i2], SCL2, ef));
                        SB[nt][hb*2 + i2] = p;
                        Lr[hb] += p;
                    }
            }
            // repack P -> A frags (2 k-chunks of 16 keys)
            uint32_t ap[2][4];
#pragma unroll
            for (int q = 0; q < 2; q++) {
                ap[q][0] = pbf2(SB[2*q][0],   SB[2*q][1]);
                ap[q][1] = pbf2(SB[2*q][2],   SB[2*q][3]);
                ap[q][2] = pbf2(SB[2*q+1][0], SB[2*q+1][1]);
                ap[q][3] = pbf2(SB[2*q+1][2], SB[2*q+1][3]);
            }
            // CTX += P @ X(rows mb..mb+31), trans-X B loads double-buffered
            {
                uint32_t cb[2][4][4];
#pragma unroll
                for (int p = 0; p < 4; p++)
                    ldsm4t(cb[0][p], sbu + OFF_XN + ((mb + tR)*XN_P + p*16 + tC)*2);
#pragma unroll
                for (int k0 = 0; k0 < 2; k0++) {
                    if (k0 == 0)
#pragma unroll
                        for (int p = 0; p < 4; p++)
                            ldsm4t(cb[1][p],
                                   sbu + OFF_XN + ((mb + 16 + tR)*XN_P + p*16 + tC)*2);
#pragma unroll
                    for (int p = 0; p < 4; p++) {
                        mma16(CA[2*p],   ap[k0], cb[k0][p][0], cb[k0][p][1]);
                        mma16(CA[2*p+1], ap[k0], cb[k0][p][2], cb[k0][p][3]);
                    }
                }
            }
        }
    }
    // row-sum reduce (once), normalize ctx, repack to A frags
    uint32_t actx[4][4];
    {
#pragma unroll
        for (int hb = 0; hb < 2; hb++) {
            Lr[hb] += __shfl_xor_sync(~0u, Lr[hb], 1);
            Lr[hb] += __shfl_xor_sync(~0u, Lr[hb], 2);
        }
        float i0 = 1.f / Lr[0], i1 = 1.f / Lr[1];
#pragma unroll
        for (int q = 0; q < 4; q++) {
            actx[q][0] = pbf2(CA[2*q][0]*i0,   CA[2*q][1]*i0);
            actx[q][1] = pbf2(CA[2*q][2]*i1,   CA[2*q][3]*i1);
            actx[q][2] = pbf2(CA[2*q+1][0]*i0, CA[2*q+1][1]*i0);
            actx[q][3] = pbf2(CA[2*q+1][2]*i1, CA[2*q+1][3]*i1);
        }
    }

    // ---- Phase C: T = relu(ctx@W1 + b1)@W2; W staged per 32-h chunk --------
    {
        float TA[8][4];
#pragma unroll
        for (int nt = 0; nt < 8; nt++)
#pragma unroll
            for (int i = 0; i < 4; i++) TA[nt][i] = 0.f;
#pragma unroll 1
        for (int ck = 0; ck < 4; ck++) {
            const int h0 = ck * 32;
            // stage W1 chunk [hl][d] and W2 chunk [d][hl] (union with M)
            __syncthreads();   // prior chunk (or Phase A's M) fully consumed
            for (int j = t; j < 1024; j += 128) {
                int hl = j >> 5, d2 = (j & 31) * 2;
                *(uint32_t*)(smb + OFF_W1C + (hl*W1C_P + d2)*2) =
                    pbf2(__ldg(&W1g[r*8192 + d2*128 + h0 + hl]),
                         __ldg(&W1g[r*8192 + (d2+1)*128 + h0 + hl]));
            }
            for (int j = t; j < 1024; j += 128) {
                int d = j >> 4, hl2 = (j & 15) * 2;
                *(uint32_t*)(smb + OFF_W2C + (d*W2C_P + hl2)*2) =
                    pbf2(__ldg(&W2g[r*8192 + (h0 + hl2)*64 + d]),
                         __ldg(&W2g[r*8192 + (h0 + hl2 + 1)*64 + d]));
            }
            __syncthreads();   // chunk staged

            float HA[4][4];
#pragma unroll
            for (int q = 0; q < 4; q++)
#pragma unroll
                for (int i = 0; i < 4; i++) HA[q][i] = 0.f;
            // H chunk = ctx @ W1c, double-buffered W1 loads
            {
                uint32_t wb[2][2][4];
#pragma unroll
                for (int q = 0; q < 2; q++)
                    ldsm4(wb[0][q], sbu + OFF_W1C + ((q*16 + bRow)*W1C_P + bKof)*2);
#pragma unroll
                for (int k0 = 0; k0 < 4; k0++) {
                    if (k0 < 3)
#pragma unroll
                        for (int q = 0; q < 2; q++)
                            ldsm4(wb[(k0+1)&1][q],
                                  sbu + OFF_W1C + ((q*16 + bRow)*W1C_P + (k0+1)*16 + bKof)*2);
#pragma unroll
                    for (int q = 0; q < 2; q++) {
                        mma16(HA[2*q],   actx[k0], wb[k0&1][q][0], wb[k0&1][q][1]);
                        mma16(HA[2*q+1], actx[k0], wb[k0&1][q][2], wb[k0&1][q][3]);
                    }
                }
            }
            // bias + relu + repack H -> A frags (two 16-h chunks)
            uint32_t ah[2][4];
#pragma unroll
            for (int hc = 0; hc < 2; hc++) {
                int base = h0 + hc*16;
                float bA0 = __ldg(&b1g[r*HDIM + base + 2*t4]);
                float bA1 = __ldg(&b1g[r*HDIM + base + 2*t4 + 1]);
                float bB0 = __ldg(&b1g[r*HDIM + base + 8 + 2*t4]);
                float bB1 = __ldg(&b1g[r*HDIM + base + 8 + 2*t4 + 1]);
                ah[hc][0] = pbf2(fmaxf(HA[2*hc][0] + bA0, 0.f),   fmaxf(HA[2*hc][1] + bA1, 0.f));
                ah[hc][1] = pbf2(fmaxf(HA[2*hc][2] + bA0, 0.f),   fmaxf(HA[2*hc][3] + bA1, 0.f));
                ah[hc][2] = pbf2(fmaxf(HA[2*hc+1][0] + bB0, 0.f), fmaxf(HA[2*hc+1][1] + bB1, 0.f));
                ah[hc][3] = pbf2(fmaxf(HA[2*hc+1][2] + bB0, 0.f), fmaxf(HA[2*hc+1][3] + bB1, 0.f));
            }
            // T += Hc @ W2c, double-buffered W2 loads
            {
                uint32_t vb[2][4][4];
#pragma unroll
                for (int p = 0; p < 4; p++)
                    ldsm4(vb[0][p], sbu + OFF_W2C + ((p*16 + bRow)*W2C_P + bKof)*2);
#pragma unroll
                for (int hc = 0; hc < 2; hc++) {
                    if (hc == 0)
#pragma unroll
                        for (int p = 0; p < 4; p++)
                            ldsm4(vb[1][p],
                                  sbu + OFF_W2C + ((p*16 + bRow)*W2C_P + 16 + bKof)*2);
#pragma unroll
                    for (int p = 0; p < 4; p++) {
                        mma16(TA[2*p],   ah[hc], vb[hc][p][0], vb[hc][p][1]);
                        mma16(TA[2*p+1], ah[hc], vb[hc][p][2], vb[hc][p][3]);
                    }
                }
            }
        }
        // ---- epilogue: g_t[r][b][n][d] = gate * (T + b2) -------------------
        const float gv = gateS[r];
        float* outp = g_t + ((size_t)(r*BB + b)) * DD * NN;
#pragma unroll
        for (int nt = 0; nt < 8; nt++) {
            int d0 = nt*8 + 2*t4;
            float b20 = __ldg(&b2g[r*DD + d0]);
            float b21 = __ldg(&b2g[r*DD + d0 + 1]);
            float2 v0 = make_float2((TA[nt][0] + b20)*gv, (TA[nt][1] + b21)*gv);
            float2 v1 = make_float2((TA[nt][2] + b20)*gv, (TA[nt][3] + b21)*gv);
            *(float2*)(outp + (row0 + g)*DD + d0)     = v0;
            *(float2*)(outp + (row0 + 8 + g)*DD + d0) = v1;
        }
    }
}

// ---------------- deterministic reduction over rules + residual --------------
__global__ void k_reduce(int cur) {
    int i = blockIdx.x * 256 + threadIdx.x;
    float s = g_x[cur][i];
#pragma unroll
    for (int rr = 0; rr < RR; rr++) s += __ldg(&g_t[(size_t)rr * BDN + i]);
    g_x[cur ^ 1][i] = s;
}

// ---------------- writeback: [b][n][d] -> output [b][d][n] -------------------
__global__ void k_out(int cur, float* __restrict__ out) {
    int i = blockIdx.x * 256 + threadIdx.x;
    int b = i >> 14, rem = i & 16383, n = rem >> 6, d = rem & 63;
    out[b*16384 + d*256 + n] = g_x[cur][i];
}

// ---------------- launch -----------------------------------------------------
extern "C" void kernel_launch(void* const* d_in, const int* in_sizes, int n_in,
                              void* d_out, int out_size) {
    const float* sym = (const float*)d_in[0];
    const float* Wq  = (const float*)d_in[1];
    const float* bq  = (const float*)d_in[2];
    const float* Wk  = (const float*)d_in[3];
    const float* bk  = (const float*)d_in[4];
    const float* W1  = (const float*)d_in[5];
    const float* b1  = (const float*)d_in[6];
    const float* W2  = (const float*)d_in[7];
    const float* b2  = (const float*)d_in[8];
    const float* Wg1 = (const float*)d_in[13];
    const float* bg1 = (const float*)d_in[14];
    const float* Wg2 = (const float*)d_in[15];
    const float* bg2 = (const float*)d_in[16];
    float* out = (float*)d_out;

    static int smem_set = 0;
    if (!smem_set) {
        cudaFuncSetAttribute(k_rule, cudaFuncAttributeMaxDynamicSharedMemorySize,
                             SMEM_BYTES);
        smem_set = 1;
    }

    k_init<<<BDN/256, 256>>>(sym);
    k_precM<<<(RR*DD*DD)/256, 256>>>(Wq, Wk);
    k_precUVC<<<RR, DD>>>(Wq, bq, Wk, bk);

    int cur = 0;
    for (int s = 0; s < STEPS; s++) {
        k_rule<<<BB*RR*4, 128, SMEM_BYTES>>>(cur, W1, b1, W2, b2, Wg1, bg1, Wg2, bg2);
        k_reduce<<<BDN/256, 256>>>(cur);
        cur ^= 1;
    }
    k_out<<<BDN/256, 256>>>(cur, out);
}

// round 12
// speedup vs baseline: 1.9573x; 1.9573x over previous
#include <cuda_runtime.h>
#include <cuda_bf16.h>
#include <cstdint>

#define BB 16
#define DD 64
#define NN 256
#define RR 32
#define HDIM 128
#define STEPS 5
#define BDN (BB*DD*NN)

// bf16 smem pitches (elements); byte pitch/16 odd -> conflict-free ldmatrix
#define XN_P 72    // x [n][d]      144 B
#define MT_P 72    // M^T [d2][d1]
#define W1_P 72    // W1^T [h][d]   144 B
#define W2_P 136   // W2^T [d][h]   272 B

// byte offsets into dynamic smem (16B aligned)
// X region [0,36864) is reused for W1 (18432) + W2 (17408) in Phase C.
#define OFF_XN  0
#define OFF_W1  0
#define OFF_W2  18432
#define OFF_M   36864    // 64*144 = 9216
#define OFF_E   46080
#define OFF_F   47104
#define OFF_U   48128
#define OFF_V   48384
#define OFF_PL  48640
#define OFF_HI  48896
#define OFF_GT  49408
#define SMEM_BYTES 49536

// 1/sqrt(128) * log2(e): softmax done in exp2 domain
#define SCL2 0.1275187959554910f

// ---------------- device globals -------------------------------------------
__device__ float g_x[2][BDN];          // state, layout [b][n][d], fp32
__device__ float g_M[RR*DD*DD];
__device__ float g_u[RR*DD];
__device__ float g_v[RR*DD];
__device__ float g_c[RR];
__device__ float g_t[(size_t)RR*BDN];  // per-rule deltas [r][b][n][d]

// ---------------- helpers ---------------------------------------------------
__device__ __forceinline__ void ldsm4(uint32_t* r, uint32_t sa) {
    asm volatile("ldmatrix.sync.aligned.m8n8.x4.shared.b16 {%0,%1,%2,%3}, [%4];"
        : "=r"(r[0]), "=r"(r[1]), "=r"(r[2]), "=r"(r[3]) : "r"(sa));
}
__device__ __forceinline__ void ldsm4t(uint32_t* r, uint32_t sa) {
    asm volatile("ldmatrix.sync.aligned.m8n8.x4.trans.shared.b16 {%0,%1,%2,%3}, [%4];"
        : "=r"(r[0]), "=r"(r[1]), "=r"(r[2]), "=r"(r[3]) : "r"(sa));
}
__device__ __forceinline__ void mma16(float* c, const uint32_t* a,
                                      uint32_t b0, uint32_t b1) {
    asm volatile("mma.sync.aligned.m16n8k16.row.col.f32.bf16.bf16.f32 "
        "{%0,%1,%2,%3}, {%4,%5,%6,%7}, {%8,%9}, {%0,%1,%2,%3};"
        : "+f"(c[0]), "+f"(c[1]), "+f"(c[2]), "+f"(c[3])
        : "r"(a[0]), "r"(a[1]), "r"(a[2]), "r"(a[3]), "r"(b0), "r"(b1));
}
__device__ __forceinline__ uint32_t pbf2(float lo, float hi) {
    __nv_bfloat162 h = __floats2bfloat162_rn(lo, hi);
    return *reinterpret_cast<uint32_t*>(&h);
}
__device__ __forceinline__ float ex2(float x) {
    float y; asm("ex2.approx.f32 %0, %1;" : "=f"(y) : "f"(x)); return y;
}

// ---------------- init: symbols [b][d][n] -> g_x[0] as [b][n][d] -------------
__global__ void k_init(const float* __restrict__ sym) {
    int i = blockIdx.x * 256 + threadIdx.x;
    int b = i >> 14, rem = i & 16383, n = rem >> 6, d = rem & 63;
    g_x[0][i] = sym[b*16384 + d*256 + n];
}

// ---------------- precompute M = Wq Wk^T ------------------------------------
__global__ void k_precM(const float* __restrict__ Wq, const float* __restrict__ Wk) {
    int i = blockIdx.x * 256 + threadIdx.x;
    int d2 = i & 63, d1 = (i >> 6) & 63, r = i >> 12;
    const float* a = Wq + (r*DD + d1) * HDIM;
    const float* bkk = Wk + (r*DD + d2) * HDIM;
    float s = 0.f;
#pragma unroll 8
    for (int h = 0; h < HDIM; h++) s = fmaf(a[h], bkk[h], s);
    g_M[i] = s;
}

__global__ void k_precUVC(const float* __restrict__ Wq, const float* __restrict__ bq,
                          const float* __restrict__ Wk, const float* __restrict__ bk) {
    int r = blockIdx.x, d = threadIdx.x;
    float su = 0.f, sv = 0.f;
    const float* wqr = Wq + (r*DD + d) * HDIM;
    const float* wkr = Wk + (r*DD + d) * HDIM;
    const float* bqr = bq + r * HDIM;
    const float* bkr = bk + r * HDIM;
#pragma unroll 8
    for (int h = 0; h < HDIM; h++) {
        su = fmaf(wqr[h], bkr[h], su);
        sv = fmaf(bqr[h], wkr[h], sv);
    }
    g_u[r*DD + d] = su;
    g_v[r*DD + d] = sv;
    if (d == 0) {
        float sc = 0.f;
        for (int h = 0; h < HDIM; h++) sc = fmaf(bqr[h], bkr[h], sc);
        g_c[r] = sc;
    }
}

// ---------------- fused rule kernel: 2 CTAs per (b,r), 3 CTAs/SM -------------
__global__ void __launch_bounds__(256, 3)
k_rule(int cur,
       const float* __restrict__ W1g, const float* __restrict__ b1g,
       const float* __restrict__ W2g, const float* __restrict__ b2g,
       const float* __restrict__ Wg1, const float* __restrict__ bg1,
       const float* __restrict__ Wg2, const float* __restrict__ bg2) {
    extern __shared__ char smb[];
    const uint32_t sbu = (uint32_t)__cvta_generic_to_shared(smb);
    __nv_bfloat16* xNb = (__nv_bfloat16*)(smb + OFF_XN);
    float* eS    = (float*)(smb + OFF_E);
    float* fS    = (float*)(smb + OFF_F);
    float* uS    = (float*)(smb + OFF_U);
    float* vS    = (float*)(smb + OFF_V);
    float* poolS = (float*)(smb + OFF_PL);
    float* hidS  = (float*)(smb + OFF_HI);
    float* gateS = (float*)(smb + OFF_GT);

    const int t = threadIdx.x;
    const int lane = t & 31, w = t >> 5;        // 8 warps
    const int g = lane >> 2, t4 = lane & 3;
    const int idx = blockIdx.x >> 1, rhalf = blockIdx.x & 1;
    const int r = idx & (RR - 1), b = idx >> 5;
    const int row0 = rhalf * 128 + w * 16;      // this warp's 16 query rows

    // ldmatrix lane offsets
    const int aRow = lane & 15;                            // A x4
    const int aKof = (lane >> 4) << 3;
    const int bRow = (lane & 7) + ((lane >> 4) << 3);      // B x4 (normal)
    const int bKof = ((lane >> 3) & 1) << 3;
    const int tR   = (lane & 7) + (((lane >> 3) & 1) << 3); // B x4 (trans)
    const int tC   = ((lane >> 4) & 1) << 3;

    const float* xg = g_x[cur] + (size_t)b * NN * DD;

    // ---- prologue: stage x (full 256 tokens), M^T, u, v --------------------
    for (int j = t; j < NN*DD/2; j += 256) {
        int n = j >> 5, d2 = (j & 31) * 2;
        *(uint32_t*)(smb + OFF_XN + (n*XN_P + d2)*2) = pbf2(xg[n*DD + d2], xg[n*DD + d2 + 1]);
    }
    for (int i = t; i < DD*DD; i += 256) {
        int d1 = i >> 6, d2 = i & 63;
        ((__nv_bfloat16*)(smb + OFF_M))[d2*MT_P + d1] = __float2bfloat16_rn(g_M[r*DD*DD + i]);
    }
    if (t < DD) { uS[t] = g_u[r*DD + t]; vS[t] = g_v[r*DD + t]; }
    __syncthreads();

    // ---- e/f for all 256 tokens (thread t -> token t) ----------------------
    {
        float ea = 0.f, fa = 0.f;
#pragma unroll 8
        for (int d = 0; d < DD; d++) {
            float xv = __bfloat162float(xNb[t*XN_P + d]);
            ea = fmaf(xv, uS[d], ea);
            fa = fmaf(xv, vS[d], fa);
        }
        eS[t] = (ea + g_c[r]) * SCL2;
        fS[t] = fa * SCL2;
    }
    __syncthreads();
    // ---- pooled mean: 4 threads per channel --------------------------------
    {
        int d = t >> 2, q = t & 3;
        float s = 0.f;
#pragma unroll 8
        for (int n = q*64; n < q*64 + 64; n++) s += __bfloat162float(xNb[n*XN_P + d]);
        s += __shfl_xor_sync(~0u, s, 1);
        s += __shfl_xor_sync(~0u, s, 2);
        if (q == 0) poolS[d] = s * (1.f/NN);
    }
    __syncthreads();
    if (t < HDIM) {
        float acc = bg1[t];
#pragma unroll 8
        for (int d = 0; d < DD; d++) acc = fmaf(poolS[d], __ldg(&Wg1[d*HDIM + t]), acc);
        hidS[t] = fmaxf(acc, 0.f);
    }
    __syncthreads();
    if (t < RR) {
        float lg = bg2[t];
#pragma unroll 8
        for (int j = 0; j < HDIM; j++) lg = fmaf(hidS[j], __ldg(&Wg2[j*RR + t]), lg);
        float m = lg;
#pragma unroll
        for (int o = 16; o > 0; o >>= 1) m = fmaxf(m, __shfl_xor_sync(~0u, m, o));
        float e = __expf(lg - m), ss = e;
#pragma unroll
        for (int o = 16; o > 0; o >>= 1) ss += __shfl_xor_sync(~0u, ss, o);
        gateS[t] = e / ss;
    }
    __syncthreads();

    // ---- Phase A: sx = X @ M -> registers, repack to A frags ----------------
    uint32_t asx[4][4];
    {
        uint32_t ax[4][4];
#pragma unroll
        for (int k0 = 0; k0 < 4; k0++)
            ldsm4(ax[k0], sbu + OFF_XN + ((row0 + aRow)*XN_P + k0*16 + aKof)*2);
        float SA[8][4];
#pragma unroll
        for (int nt = 0; nt < 8; nt++)
#pragma unroll
            for (int i = 0; i < 4; i++) SA[nt][i] = 0.f;
#pragma unroll
        for (int k0 = 0; k0 < 4; k0++) {
            uint32_t mb_[4][4];
#pragma unroll
            for (int p = 0; p < 4; p++)
                ldsm4(mb_[p], sbu + OFF_M + ((p*16 + bRow)*MT_P + k0*16 + bKof)*2);
#pragma unroll
            for (int p = 0; p < 4; p++) {
                mma16(SA[2*p],   ax[k0], mb_[p][0], mb_[p][1]);
                mma16(SA[2*p+1], ax[k0], mb_[p][2], mb_[p][3]);
            }
        }
#pragma unroll
        for (int j = 0; j < 4; j++) {
            asx[j][0] = pbf2(SA[2*j][0],   SA[2*j][1]);
            asx[j][1] = pbf2(SA[2*j][2],   SA[2*j][3]);
            asx[j][2] = pbf2(SA[2*j+1][0], SA[2*j+1][1]);
            asx[j][3] = pbf2(SA[2*j+1][2], SA[2*j+1][3]);
        }
    }

    // ---- Phase B: attention, 32-wide key blocks ----------------------------
    float CA[8][4];
    float Lr[2] = {0.f, 0.f};
#pragma unroll
    for (int nt = 0; nt < 8; nt++)
#pragma unroll
        for (int i = 0; i < 4; i++) CA[nt][i] = 0.f;
    {
#pragma unroll 1
        for (int j = 0; j < 8; j++) {
            const int mb = j * 32;
            float SB[4][4];
#pragma unroll
            for (int nt = 0; nt < 4; nt++)
#pragma unroll
                for (int i = 0; i < 4; i++) SB[nt][i] = 0.f;
            // S = sx @ X^T (32 key cols)
#pragma unroll
            for (int k0 = 0; k0 < 4; k0++) {
                uint32_t bb[2][4];
#pragma unroll
                for (int p = 0; p < 2; p++)
                    ldsm4(bb[p], sbu + OFF_XN + ((mb + p*16 + bRow)*XN_P + k0*16 + bKof)*2);
#pragma unroll
                for (int p = 0; p < 2; p++) {
                    mma16(SB[2*p],   asx[k0], bb[p][0], bb[p][1]);
                    mma16(SB[2*p+1], asx[k0], bb[p][2], bb[p][3]);
                }
            }
            // p = exp2(S*SCL2 + e' + f');  Lr += p
#pragma unroll
            for (int hb = 0; hb < 2; hb++) {
                const float er = eS[row0 + hb*8 + g];
#pragma unroll
                for (int nt = 0; nt < 4; nt++)
#pragma unroll
                    for (int i2 = 0; i2 < 2; i2++) {
                        float ef = er + fS[mb + nt*8 + 2*t4 + i2];
                        float p = ex2(fmaf(SB[nt][hb*2 + i2], SCL2, ef));
                        SB[nt][hb*2 + i2] = p;
                        Lr[hb] += p;
                    }
            }
            // repack P -> A frags (2 k-chunks of 16 keys)
            uint32_t ap[2][4];
#pragma unroll
            for (int q = 0; q < 2; q++) {
                ap[q][0] = pbf2(SB[2*q][0],   SB[2*q][1]);
                ap[q][1] = pbf2(SB[2*q][2],   SB[2*q][3]);
                ap[q][2] = pbf2(SB[2*q+1][0], SB[2*q+1][1]);
                ap[q][3] = pbf2(SB[2*q+1][2], SB[2*q+1][3]);
            }
            // CTX += P @ X(rows mb..mb+31), trans-X B loads
#pragma unroll
            for (int k0 = 0; k0 < 2; k0++) {
                uint32_t cb[4][4];
#pragma unroll
                for (int p = 0; p < 4; p++)
                    ldsm4t(cb[p], sbu + OFF_XN + ((mb + k0*16 + tR)*XN_P + p*16 + tC)*2);
#pragma unroll
                for (int p = 0; p < 4; p++) {
                    mma16(CA[2*p],   ap[k0], cb[p][0], cb[p][1]);
                    mma16(CA[2*p+1], ap[k0], cb[p][2], cb[p][3]);
                }
            }
        }
    }
    // row-sum reduce (once), normalize ctx, repack to A frags
    uint32_t actx[4][4];
    {
#pragma unroll
        for (int hb = 0; hb < 2; hb++) {
            Lr[hb] += __shfl_xor_sync(~0u, Lr[hb], 1);
            Lr[hb] += __shfl_xor_sync(~0u, Lr[hb], 2);
        }
        float i0 = 1.f / Lr[0], i1 = 1.f / Lr[1];
#pragma unroll
        for (int q = 0; q < 4; q++) {
            actx[q][0] = pbf2(CA[2*q][0]*i0,   CA[2*q][1]*i0);
            actx[q][1] = pbf2(CA[2*q][2]*i1,   CA[2*q][3]*i1);
            actx[q][2] = pbf2(CA[2*q+1][0]*i0, CA[2*q+1][1]*i0);
            actx[q][3] = pbf2(CA[2*q+1][2]*i1, CA[2*q+1][3]*i1);
        }
    }

    // ---- stage W1/W2 into the (now dead) X region --------------------------
    __syncthreads();    // all warps done reading X
    for (int i = t; i < DD*HDIM; i += 256) {
        int d = i >> 7, h = i & 127;
        ((__nv_bfloat16*)(smb + OFF_W1))[h*W1_P + d] = __float2bfloat16_rn(__ldg(&W1g[r*DD*HDIM + i]));
    }
    for (int i = t; i < HDIM*DD; i += 256) {
        int h = i >> 6, d = i & 63;
        ((__nv_bfloat16*)(smb + OFF_W2))[d*W2_P + h] = __float2bfloat16_rn(__ldg(&W2g[r*HDIM*DD + i]));
    }
    __syncthreads();

    // ---- Phase C: T = relu(ctx@W1 + b1)@W2, 32-h chunks --------------------
    {
        float TA[8][4];
#pragma unroll
        for (int nt = 0; nt < 8; nt++)
#pragma unroll
            for (int i = 0; i < 4; i++) TA[nt][i] = 0.f;
#pragma unroll 1
        for (int ck = 0; ck < 4; ck++) {
            const int h0 = ck * 32;
            float HA[4][4];
#pragma unroll
            for (int q = 0; q < 4; q++)
#pragma unroll
                for (int i = 0; i < 4; i++) HA[q][i] = 0.f;
            // H chunk = ctx @ W1[:, h0:h0+32]
#pragma unroll
            for (int k0 = 0; k0 < 4; k0++) {
                uint32_t wb[2][4];
#pragma unroll
                for (int q = 0; q < 2; q++)
                    ldsm4(wb[q], sbu + OFF_W1 + ((h0 + q*16 + bRow)*W1_P + k0*16 + bKof)*2);
#pragma unroll
                for (int q = 0; q < 2; q++) {
                    mma16(HA[2*q],   actx[k0], wb[q][0], wb[q][1]);
                    mma16(HA[2*q+1], actx[k0], wb[q][2], wb[q][3]);
                }
            }
            // bias + relu + repack H -> A frags (two 16-h chunks)
            uint32_t ah[2][4];
#pragma unroll
            for (int hc = 0; hc < 2; hc++) {
                int base = h0 + hc*16;
                float bA0 = __ldg(&b1g[r*HDIM + base + 2*t4]);
                float bA1 = __ldg(&b1g[r*HDIM + base + 2*t4 + 1]);
                float bB0 = __ldg(&b1g[r*HDIM + base + 8 + 2*t4]);
                float bB1 = __ldg(&b1g[r*HDIM + base + 8 + 2*t4 + 1]);
                ah[hc][0] = pbf2(fmaxf(HA[2*hc][0] + bA0, 0.f),   fmaxf(HA[2*hc][1] + bA1, 0.f));
                ah[hc][1] = pbf2(fmaxf(HA[2*hc][2] + bA0, 0.f),   fmaxf(HA[2*hc][3] + bA1, 0.f));
                ah[hc][2] = pbf2(fmaxf(HA[2*hc+1][0] + bB0, 0.f), fmaxf(HA[2*hc+1][1] + bB1, 0.f));
                ah[hc][3] = pbf2(fmaxf(HA[2*hc+1][2] + bB0, 0.f), fmaxf(HA[2*hc+1][3] + bB1, 0.f));
            }
            // T += H @ W2[h0:h0+32, :]
#pragma unroll
            for (int hc = 0; hc < 2; hc++) {
                uint32_t vb[4][4];
#pragma unroll
                for (int p = 0; p < 4; p++)
                    ldsm4(vb[p], sbu + OFF_W2 + ((p*16 + bRow)*W2_P + h0 + hc*16 + bKof)*2);
#pragma unroll
                for (int p = 0; p < 4; p++) {
                    mma16(TA[2*p],   ah[hc], vb[p][0], vb[p][1]);
                    mma16(TA[2*p+1], ah[hc], vb[p][2], vb[p][3]);
                }
            }
        }
        // ---- epilogue: g_t[r][b][n][d] = gate * (T + b2) -------------------
        const float gv = gateS[r];
        float* outp = g_t + ((size_t)(r*BB + b)) * DD * NN;
#pragma unroll
        for (int nt = 0; nt < 8; nt++) {
            int d0 = nt*8 + 2*t4;
            float b20 = __ldg(&b2g[r*DD + d0]);
            float b21 = __ldg(&b2g[r*DD + d0 + 1]);
            float2 v0 = make_float2((TA[nt][0] + b20)*gv, (TA[nt][1] + b21)*gv);
            float2 v1 = make_float2((TA[nt][2] + b20)*gv, (TA[nt][3] + b21)*gv);
            *(float2*)(outp + (row0 + g)*DD + d0)     = v0;
            *(float2*)(outp + (row0 + 8 + g)*DD + d0) = v1;
        }
    }
}

// ---------------- deterministic reduction over rules + residual --------------
__global__ void k_reduce(int cur) {
    int i = blockIdx.x * 256 + threadIdx.x;
    float s = g_x[cur][i];
#pragma unroll
    for (int rr = 0; rr < RR; rr++) s += __ldg(&g_t[(size_t)rr * BDN + i]);
    g_x[cur ^ 1][i] = s;
}

// ---------------- writeback: [b][n][d] -> output [b][d][n] -------------------
__global__ void k_out(int cur, float* __restrict__ out) {
    int i = blockIdx.x * 256 + threadIdx.x;
    int b = i >> 14, rem = i & 16383, n = rem >> 6, d = rem & 63;
    out[b*16384 + d*256 + n] = g_x[cur][i];
}

// ---------------- launch -----------------------------------------------------
extern "C" void kernel_launch(void* const* d_in, const int* in_sizes, int n_in,
                              void* d_out, int out_size) {
    const float* sym = (const float*)d_in[0];
    const float* Wq  = (const float*)d_in[1];
    const float* bq  = (const float*)d_in[2];
    const float* Wk  = (const float*)d_in[3];
    const float* bk  = (const float*)d_in[4];
    const float* W1  = (const float*)d_in[5];
    const float* b1  = (const float*)d_in[6];
    const float* W2  = (const float*)d_in[7];
    const float* b2  = (const float*)d_in[8];
    const float* Wg1 = (const float*)d_in[13];
    const float* bg1 = (const float*)d_in[14];
    const float* Wg2 = (const float*)d_in[15];
    const float* bg2 = (const float*)d_in[16];
    float* out = (float*)d_out;

    static int smem_set = 0;
    if (!smem_set) {
        cudaFuncSetAttribute(k_rule, cudaFuncAttributeMaxDynamicSharedMemorySize,
                             SMEM_BYTES);
        smem_set = 1;
    }

    k_init<<<BDN/256, 256>>>(sym);
    k_precM<<<(RR*DD*DD)/256, 256>>>(Wq, Wk);
    k_precUVC<<<RR, DD>>>(Wq, bq, Wk, bk);

    int cur = 0;
    for (int s = 0; s < STEPS; s++) {
        k_rule<<<BB*RR*2, 256, SMEM_BYTES>>>(cur, W1, b1, W2, b2, Wg1, bg1, Wg2, bg2);
        k_reduce<<<BDN/256, 256>>>(cur);
        cur ^= 1;
    }
    k_out<<<BDN/256, 256>>>(cur, out);
}